// round 13
// baseline (speedup 1.0000x reference)
#include <cuda_runtime.h>
#include <cuda_fp16.h>
#include <math.h>
#include <stdint.h>

#define H     1024
#define NEXP  8
#define MAXT  8192
#define MAXROWS (MAXT * 2)

#define BK      64
#define NK      (H / BK)      // 16 k-tiles
#define TILE_M  128
#define TILE_N  128
#define NSTAGE  3

// SMEM stage: 2 buffers (A, B) of 128 rows x 144B (64 fp16 + 16B pad)
#define ROWB        144
#define BUF_BYTES   (128 * ROWB)        // 18432
#define OFF_A       0
#define OFF_B       BUF_BYTES
#define STAGE_BYTES (2 * BUF_BYTES)     // 36864
#define SMEM_TOTAL  (NSTAGE * STAGE_BYTES)   // 110592; 2 CTAs = 216KB <= 228KB carveout

// ---------------- scratch (device globals; no runtime allocation) ----------------
__device__ float  g_bufA[(size_t)MAXROWS * H];          // layer3 weighted partials
__device__ __half g_a1[(size_t)MAXROWS * H];            // layer1 out (fp16)
__device__ __half g_a2[(size_t)MAXROWS * H];            // layer2 out (fp16)
__device__ __half g_xh[(size_t)MAXT * H];               // x in fp16
__device__ __half g_wt[(size_t)3 * NEXP * H * H];       // [l][e][n][k] fp16 weights
__device__ int   g_cnt[NEXP];
__device__ int   g_off[NEXP];
__device__ int   g_fill[NEXP];
__device__ int   g_done;
__device__ int   g_row_tok[MAXROWS];
__device__ float g_row_w[MAXROWS];
__device__ int   g_tok_pos[MAXROWS];
__device__ int   g_tmp_e[MAXROWS];
__device__ float g_tmp_w[MAXROWS];

// ---------------- helpers ----------------
__device__ __forceinline__ uint32_t smem_u32(const void* p) {
    uint32_t a;
    asm("{ .reg .u64 t; cvta.to.shared.u64 t, %1; cvt.u32.u64 %0, t; }" : "=r"(a) : "l"(p));
    return a;
}
__device__ __forceinline__ void cp16(uint32_t dst, const void* src, uint32_t sz) {
    asm volatile("cp.async.cg.shared.global [%0], [%1], 16, %2;"
                 :: "r"(dst), "l"(src), "r"(sz) : "memory");
}
__device__ __forceinline__ void cp_commit() { asm volatile("cp.async.commit_group;" ::: "memory"); }
template <int N>
__device__ __forceinline__ void cp_wait() { asm volatile("cp.async.wait_group %0;" :: "n"(N) : "memory"); }

__device__ __forceinline__ void mma_f16(float* d, const uint32_t* a, const uint32_t* b) {
    asm volatile("mma.sync.aligned.m16n8k16.row.col.f32.f16.f16.f32 "
        "{%0,%1,%2,%3}, {%4,%5,%6,%7}, {%8,%9}, {%0,%1,%2,%3};"
        : "+f"(d[0]), "+f"(d[1]), "+f"(d[2]), "+f"(d[3])
        : "r"(a[0]), "r"(a[1]), "r"(a[2]), "r"(a[3]), "r"(b[0]), "r"(b[1]));
}
__device__ __forceinline__ void ldsm4(uint32_t* r, uint32_t addr) {
    asm volatile("ldmatrix.sync.aligned.m8n8.x4.shared.b16 {%0,%1,%2,%3}, [%4];"
        : "=r"(r[0]), "=r"(r[1]), "=r"(r[2]), "=r"(r[3]) : "r"(addr));
}
__device__ __forceinline__ uint32_t pkh(__half a, __half b) {
    __half2 t = __halves2half2(a, b);
    return *reinterpret_cast<uint32_t*>(&t);
}

// ---------------- router: logits, top-2, x->fp16, tail offsets ----------------
__global__ void k_router(const float* __restrict__ x, const float* __restrict__ gw,
                         const float* __restrict__ gb, float* __restrict__ logits_out, int T) {
    int warp = (blockIdx.x * blockDim.x + threadIdx.x) >> 5;
    int lane = threadIdx.x & 31;
    if (warp < T) {
        const float* xr = x + (size_t)warp * H;
        float acc[NEXP];
#pragma unroll
        for (int e = 0; e < NEXP; e++) acc[e] = 0.f;
        for (int h = lane * 2; h < H; h += 64) {
            float2 xv = *reinterpret_cast<const float2*>(xr + h);
            const float4* g0 = reinterpret_cast<const float4*>(gw + (size_t)h * NEXP);
            float4 a = __ldg(g0), b = __ldg(g0 + 1), c = __ldg(g0 + 2), d = __ldg(g0 + 3);
            acc[0] += xv.x * a.x + xv.y * c.x;  acc[1] += xv.x * a.y + xv.y * c.y;
            acc[2] += xv.x * a.z + xv.y * c.z;  acc[3] += xv.x * a.w + xv.y * c.w;
            acc[4] += xv.x * b.x + xv.y * d.x;  acc[5] += xv.x * b.y + xv.y * d.y;
            acc[6] += xv.x * b.z + xv.y * d.z;  acc[7] += xv.x * b.w + xv.y * d.w;
            *reinterpret_cast<uint32_t*>(g_xh + (size_t)warp * H + h) =
                pkh(__float2half(xv.x), __float2half(xv.y));
        }
#pragma unroll
        for (int e = 0; e < NEXP; e++)
#pragma unroll
            for (int o = 16; o > 0; o >>= 1)
                acc[e] += __shfl_xor_sync(0xffffffffu, acc[e], o);

        if (lane == 0) {
            float lg[NEXP];
#pragma unroll
            for (int e = 0; e < NEXP; e++) {
                lg[e] = acc[e] + gb[e];
                if (logits_out) logits_out[(size_t)warp * NEXP + e] = lg[e];
            }
            int i1 = 0;
#pragma unroll
            for (int e = 1; e < NEXP; e++) if (lg[e] > lg[i1]) i1 = e;
            int i2 = (i1 == 0) ? 1 : 0;
#pragma unroll
            for (int e = 0; e < NEXP; e++) { if (e == i1) continue; if (lg[e] > lg[i2]) i2 = e; }
            float p2 = expf(lg[i2] - lg[i1]);
            float inv = 1.f / (1.f + p2);
            g_row_tok[warp * 2 + 0] = i1;       // expert ids keyed by (tok,k)
            g_row_tok[warp * 2 + 1] = i2;
            g_row_w[warp * 2 + 0] = inv;        // weights keyed by (tok,k)
            g_row_w[warp * 2 + 1] = p2 * inv;
            atomicAdd(&g_cnt[i1], 1);
            atomicAdd(&g_cnt[i2], 1);
        }
    }
    // ---- tail: last block computes expert offsets ----
    __threadfence();
    __syncthreads();
    if (threadIdx.x == 0) {
        int ticket = atomicAdd(&g_done, 1);
        if (ticket == (int)gridDim.x - 1) {
            int s = 0;
#pragma unroll
            for (int e = 0; e < NEXP; e++) { g_off[e] = s; s += g_cnt[e]; g_fill[e] = 0; }
            g_done = 0;
            __threadfence();
        }
    }
}

__global__ void k_scatter(int T) {
    int i = blockIdx.x * blockDim.x + threadIdx.x;
    if (i >= 2 * T) return;
    int e = g_row_tok[i];
    float w = g_row_w[i];
    int pos = g_off[e] + atomicAdd(&g_fill[e], 1);
    g_tmp_e[pos] = i >> 1;     // token index, gathered order
    g_tmp_w[pos] = w;
    g_tok_pos[i] = pos;
}

// ---------------- fused weight transpose + fp16 convert (all 3 layers) ----------------
__global__ void k_split_w3(const float* __restrict__ w1, const float* __restrict__ w2,
                           const float* __restrict__ w3) {
    __shared__ float t[32][33];
    int lz = blockIdx.z;
    int layer = lz >> 3, e = lz & 7;
    const float* W = (layer == 0) ? w1 : ((layer == 1) ? w2 : w3);
    int kb = blockIdx.y * 32, nb = blockIdx.x * 32;
    const float* We = W + (size_t)e * H * H;
    int tx = threadIdx.x, ty = threadIdx.y;   // 32 x 8
#pragma unroll
    for (int i = 0; i < 32; i += 8)
        t[ty + i][tx] = We[(size_t)(kb + ty + i) * H + nb + tx];
    __syncthreads();
    size_t obase = ((size_t)layer * NEXP + e) * H * H;
    __half* he = g_wt + obase;
#pragma unroll
    for (int i = 0; i < 32; i += 8)
        he[(size_t)(nb + ty + i) * H + kb + tx] = __float2half(t[tx][ty + i]);
}

// ---------------- HMMA single-pass fp16 gathered expert GEMM ----------------
// Inner loop: per kp, ALL 6 ldsm issued back-to-back (MLP=6, one scoreboard
// drain), then 16 MMAs dependency-free. asm volatile pins this order in SASS,
// cutting ldsm->mma latency exposure from 16 points/kt (R9/R10) to 4.
template <int LAYER>
__global__ __launch_bounds__(256, 2)
void k_gemm_mma(int layer, const float* __restrict__ Bias, int T) {
    int e = blockIdx.z;
    int cnt = g_cnt[e];
    int row0 = blockIdx.y * TILE_M;
    if (row0 >= cnt) return;
    int base = g_off[e];
    int col0 = blockIdx.x * TILE_N;
    int tid = threadIdx.x;
    int wid = tid >> 5, lane = tid & 31;
    int wm = wid & 1, wn = wid >> 1;       // warp tile: rows wm*64, cols wn*32
    int r1 = lane >> 2, cq = lane & 3;

    extern __shared__ char smem[];
    uint32_t sb = smem_u32(smem);

    // ---- per-thread load setup (2 threads per row, 64B halves) ----
    int lrow = tid >> 1, lhalf = tid & 1;
    int agrow = row0 + lrow;
    bool aval = (agrow < cnt);
    long aridx = 0;
    if (aval) aridx = (LAYER == 1) ? (long)g_tmp_e[base + agrow] : (long)(base + agrow);
    const __half* pA = (LAYER == 1) ? g_xh : ((LAYER == 2) ? g_a1 : g_a2);
    const char* gA = (const char*)(pA + (size_t)aridx * H) + lhalf * 64;
    uint32_t aSz = aval ? 16u : 0u;   // src-size 0 => zero-fill

    size_t wbase = ((size_t)layer * NEXP + e) * H * H;
    const char* gB = (const char*)(g_wt + wbase + (size_t)(col0 + lrow) * H) + lhalf * 64;

    uint32_t sdstA = sb + OFF_A + lrow * ROWB + lhalf * 64;
    uint32_t sdstB = sb + OFF_B + lrow * ROWB + lhalf * 64;

    // ldmatrix per-thread row offsets (144B stride: conflict-free)
    int lg = lane >> 3, lr = lane & 7;
    uint32_t aRowOff = (uint32_t)((((lg & 1) << 3) + lr) * ROWB + ((lg >> 1) << 4));
    uint32_t bRowOff = (uint32_t)((((lg >> 1) << 3) + lr) * ROWB + ((lg & 1) << 4));
    uint32_t aBase = OFF_A + (uint32_t)(wm * 64) * ROWB + aRowOff;
    uint32_t bBase = OFF_B + (uint32_t)(wn * 32) * ROWB + bRowOff;

    float acc[4][4][4];
#pragma unroll
    for (int i = 0; i < 4; i++)
#pragma unroll
        for (int j = 0; j < 4; j++)
#pragma unroll
            for (int r = 0; r < 4; r++) acc[i][j][r] = 0.f;

    auto loadStage = [&](int kt, int slot) {
        uint32_t so = slot * STAGE_BYTES;
        long go = (long)kt * 128;          // bytes into row (BK fp16)
#pragma unroll
        for (int q = 0; q < 4; q++) cp16(sdstA + so + q * 16, gA + go + q * 16, aSz);
#pragma unroll
        for (int q = 0; q < 4; q++) cp16(sdstB + so + q * 16, gB + go + q * 16, 16u);
    };

    // prologue: 2 stages in flight
    loadStage(0, 0); cp_commit();
    loadStage(1, 1); cp_commit();

    int cs = 0, ls = 2;     // compute slot for kt; load slot for kt+2
    for (int kt = 0; kt < NK; kt++) {
        cp_wait<1>();
        __syncthreads();
        if (kt + 2 < NK) loadStage(kt + 2, ls);
        cp_commit();

        uint32_t so = cs * STAGE_BYTES;
        uint32_t sA = sb + so + aBase;
        uint32_t sB = sb + so + bBase;

#pragma unroll
        for (int kp = 0; kp < 4; kp++) {
            uint32_t kb = kp * 32;
            uint32_t a[4][4], b[8];
            // all loads first: 6 independent ldsm, single latency drain
            ldsm4(b + 0, sB + kb);
            ldsm4(b + 4, sB + kb + 16 * ROWB);
            ldsm4(a[0], sA + kb);
            ldsm4(a[1], sA + kb + 16 * ROWB);
            ldsm4(a[2], sA + kb + 32 * ROWB);
            ldsm4(a[3], sA + kb + 48 * ROWB);
            // then 16 dependency-free MMAs
#pragma unroll
            for (int i = 0; i < 4; i++)
#pragma unroll
                for (int j = 0; j < 4; j++)
                    mma_f16(acc[i][j], a[i], b + 2 * j);
        }
        cs = (cs == 2) ? 0 : cs + 1;
        ls = (ls == 2) ? 0 : ls + 1;
    }

    // ---- epilogue ----
    const float* be = Bias + (size_t)e * H + col0 + wn * 32 + cq * 2;
    float2 bj[4];
#pragma unroll
    for (int j = 0; j < 4; j++) bj[j] = *reinterpret_cast<const float2*>(be + j * 8);

#pragma unroll
    for (int i = 0; i < 4; i++) {
        int ra = wm * 64 + i * 16 + r1;
        int rb = ra + 8;
        bool va = (row0 + ra < cnt), vb = (row0 + rb < cnt);
        long oa = (long)(base + row0 + ra) * H;
        long ob = (long)(base + row0 + rb) * H;
        float wa = 0.f, wb = 0.f;
        if (LAYER == 3) {
            if (va) wa = g_tmp_w[base + row0 + ra];
            if (vb) wb = g_tmp_w[base + row0 + rb];
        }
#pragma unroll
        for (int j = 0; j < 4; j++) {
            int col = col0 + wn * 32 + j * 8 + cq * 2;
            if (LAYER == 3) {
                if (va) *reinterpret_cast<float2*>(g_bufA + oa + col) =
                    make_float2(wa * (acc[i][j][0] + bj[j].x), wa * (acc[i][j][1] + bj[j].y));
                if (vb) *reinterpret_cast<float2*>(g_bufA + ob + col) =
                    make_float2(wb * (acc[i][j][2] + bj[j].x), wb * (acc[i][j][3] + bj[j].y));
            } else {
                __half* dh = (LAYER == 1) ? g_a1 : g_a2;
                if (va) {
                    float v0 = fmaxf(acc[i][j][0] + bj[j].x, 0.f);
                    float v1 = fmaxf(acc[i][j][1] + bj[j].y, 0.f);
                    *reinterpret_cast<uint32_t*>(dh + oa + col) =
                        pkh(__float2half(v0), __float2half(v1));
                }
                if (vb) {
                    float v0 = fmaxf(acc[i][j][2] + bj[j].x, 0.f);
                    float v1 = fmaxf(acc[i][j][3] + bj[j].y, 0.f);
                    *reinterpret_cast<uint32_t*>(dh + ob + col) =
                        pkh(__float2half(v0), __float2half(v1));
                }
            }
        }
    }
}

// ---------------- final combine (+ counter reset for next replay) ----------------
__global__ void k_combine(float* __restrict__ out, int T) {
    if (blockIdx.x == 0 && threadIdx.x < NEXP) g_cnt[threadIdx.x] = 0;
    long i = (long)blockIdx.x * blockDim.x + threadIdx.x;
    long n = (long)T * (H / 4);
    if (i >= n) return;
    int t  = (int)(i / (H / 4));
    int c4 = (int)(i % (H / 4));
    int p0 = g_tok_pos[2 * t], p1 = g_tok_pos[2 * t + 1];
    float4 a = *reinterpret_cast<const float4*>(g_bufA + (size_t)p0 * H + c4 * 4);
    float4 b = *reinterpret_cast<const float4*>(g_bufA + (size_t)p1 * H + c4 * 4);
    *reinterpret_cast<float4*>(out + (size_t)t * H + c4 * 4) =
        make_float4(a.x + b.x, a.y + b.y, a.z + b.z, a.w + b.w);
}

// ---------------- launch ----------------
// Launch index 3 = k_gemm_mma<1> (ncu -s 5 -c 1 window lands there).
extern "C" void kernel_launch(void* const* d_in, const int* in_sizes, int n_in,
                              void* d_out, int out_size) {
    const float* x  = (const float*)d_in[0];
    const float* gw = (const float*)d_in[1];
    const float* gb = (const float*)d_in[2];
    const float* w1 = (const float*)d_in[3];
    const float* b1 = (const float*)d_in[4];
    const float* w2 = (const float*)d_in[5];
    const float* b2 = (const float*)d_in[6];
    const float* w3 = (const float*)d_in[7];
    const float* b3 = (const float*)d_in[8];
    float* out = (float*)d_out;

    int T = in_sizes[0] / H;
    if (T > MAXT) T = MAXT;
    long outN = (long)T * H;
    bool has_logits = ((long)out_size >= outN + (long)T * NEXP);
    float* logits = has_logits ? out + outN : nullptr;

    cudaFuncSetAttribute(k_gemm_mma<1>, cudaFuncAttributeMaxDynamicSharedMemorySize, SMEM_TOTAL);
    cudaFuncSetAttribute(k_gemm_mma<2>, cudaFuncAttributeMaxDynamicSharedMemorySize, SMEM_TOTAL);
    cudaFuncSetAttribute(k_gemm_mma<3>, cudaFuncAttributeMaxDynamicSharedMemorySize, SMEM_TOTAL);

    k_router<<<(T * 32 + 255) / 256, 256>>>(x, gw, gb, logits, T);     // #0
    k_scatter<<<(2 * T + 255) / 256, 256>>>(T);                        // #1
    dim3 tg(32, 32, 3 * NEXP), tb(32, 8);
    k_split_w3<<<tg, tb>>>(w1, w2, w3);                                // #2

    dim3 grid(H / TILE_N, MAXT / TILE_M, NEXP);   // 8 x 64 x 8
    k_gemm_mma<1><<<grid, 256, SMEM_TOTAL>>>(0, b1, T);                // #3  <- ncu capture
    k_gemm_mma<2><<<grid, 256, SMEM_TOTAL>>>(1, b2, T);                // #4
    k_gemm_mma<3><<<grid, 256, SMEM_TOTAL>>>(2, b3, T);                // #5

    long nc = (long)T * (H / 4);
    k_combine<<<(int)((nc + 255) / 256), 256>>>(out, T);               // #6
}

// round 15
// speedup vs baseline: 1.6404x; 1.6404x over previous
#include <cuda_runtime.h>
#include <cuda_fp16.h>
#include <math.h>
#include <stdint.h>

#define H     1024
#define NEXP  8
#define MAXT  8192
#define MAXROWS (MAXT * 2)

#define BK      32
#define NK      (H / BK)      // 32 k-tiles
#define TILE_M  128
#define TILE_N  128

// SMEM stage: 2 buffers (A, B) of 128 rows x 80B (32 fp16 + 16B pad) - R7 geometry
#define ROWB        80
#define BUF_BYTES   (128 * ROWB)        // 10240
#define OFF_A       0
#define OFF_B       BUF_BYTES
#define STAGE_BYTES (2 * BUF_BYTES)     // 20480
#define SMEM_TOTAL  (2 * STAGE_BYTES)   // 40960 -> 2 CTAs/SM

// ---------------- scratch (device globals; no runtime allocation) ----------------
__device__ __half g_a1[(size_t)MAXROWS * H];            // layer1 out (fp16)
__device__ __half g_a2[(size_t)MAXROWS * H];            // layer2 out (fp16)
__device__ __half g_xh[(size_t)MAXT * H];               // x in fp16
__device__ __half g_wt[(size_t)3 * NEXP * H * H];       // [l][e][n][k] fp16 weights
__device__ int   g_cnt[NEXP];
__device__ int   g_off[NEXP];
__device__ int   g_fill[NEXP];
__device__ int   g_done;
__device__ int   g_row_tok[MAXROWS];
__device__ float g_row_w[MAXROWS];
__device__ int   g_tmp_e[MAXROWS];
__device__ float g_tmp_w[MAXROWS];

// ---------------- helpers ----------------
__device__ __forceinline__ uint32_t smem_u32(const void* p) {
    uint32_t a;
    asm("{ .reg .u64 t; cvta.to.shared.u64 t, %1; cvt.u32.u64 %0, t; }" : "=r"(a) : "l"(p));
    return a;
}
__device__ __forceinline__ void cp16(uint32_t dst, const void* src, uint32_t sz) {
    asm volatile("cp.async.cg.shared.global [%0], [%1], 16, %2;"
                 :: "r"(dst), "l"(src), "r"(sz) : "memory");
}
__device__ __forceinline__ void cp_commit() { asm volatile("cp.async.commit_group;" ::: "memory"); }
template <int N>
__device__ __forceinline__ void cp_wait() { asm volatile("cp.async.wait_group %0;" :: "n"(N) : "memory"); }

__device__ __forceinline__ void mma_f16(float* d, const uint32_t* a, const uint32_t* b) {
    asm volatile("mma.sync.aligned.m16n8k16.row.col.f32.f16.f16.f32 "
        "{%0,%1,%2,%3}, {%4,%5,%6,%7}, {%8,%9}, {%0,%1,%2,%3};"
        : "+f"(d[0]), "+f"(d[1]), "+f"(d[2]), "+f"(d[3])
        : "r"(a[0]), "r"(a[1]), "r"(a[2]), "r"(a[3]), "r"(b[0]), "r"(b[1]));
}
__device__ __forceinline__ void ldsm4(uint32_t* r, uint32_t addr) {
    asm volatile("ldmatrix.sync.aligned.m8n8.x4.shared.b16 {%0,%1,%2,%3}, [%4];"
        : "=r"(r[0]), "=r"(r[1]), "=r"(r[2]), "=r"(r[3]) : "r"(addr));
}
__device__ __forceinline__ uint32_t pkh(__half a, __half b) {
    __half2 t = __halves2half2(a, b);
    return *reinterpret_cast<uint32_t*>(&t);
}

// ---------------- router: logits, top-2, x->fp16, tail offsets ----------------
__global__ void k_router(const float* __restrict__ x, const float* __restrict__ gw,
                         const float* __restrict__ gb, float* __restrict__ logits_out, int T) {
    int warp = (blockIdx.x * blockDim.x + threadIdx.x) >> 5;
    int lane = threadIdx.x & 31;
    if (warp < T) {
        const float* xr = x + (size_t)warp * H;
        float acc[NEXP];
#pragma unroll
        for (int e = 0; e < NEXP; e++) acc[e] = 0.f;
        for (int h = lane * 2; h < H; h += 64) {
            float2 xv = *reinterpret_cast<const float2*>(xr + h);
            const float4* g0 = reinterpret_cast<const float4*>(gw + (size_t)h * NEXP);
            float4 a = __ldg(g0), b = __ldg(g0 + 1), c = __ldg(g0 + 2), d = __ldg(g0 + 3);
            acc[0] += xv.x * a.x + xv.y * c.x;  acc[1] += xv.x * a.y + xv.y * c.y;
            acc[2] += xv.x * a.z + xv.y * c.z;  acc[3] += xv.x * a.w + xv.y * c.w;
            acc[4] += xv.x * b.x + xv.y * d.x;  acc[5] += xv.x * b.y + xv.y * d.y;
            acc[6] += xv.x * b.z + xv.y * d.z;  acc[7] += xv.x * b.w + xv.y * d.w;
            *reinterpret_cast<uint32_t*>(g_xh + (size_t)warp * H + h) =
                pkh(__float2half(xv.x), __float2half(xv.y));
        }
#pragma unroll
        for (int e = 0; e < NEXP; e++)
#pragma unroll
            for (int o = 16; o > 0; o >>= 1)
                acc[e] += __shfl_xor_sync(0xffffffffu, acc[e], o);

        if (lane == 0) {
            float lg[NEXP];
#pragma unroll
            for (int e = 0; e < NEXP; e++) {
                lg[e] = acc[e] + gb[e];
                if (logits_out) logits_out[(size_t)warp * NEXP + e] = lg[e];
            }
            int i1 = 0;
#pragma unroll
            for (int e = 1; e < NEXP; e++) if (lg[e] > lg[i1]) i1 = e;
            int i2 = (i1 == 0) ? 1 : 0;
#pragma unroll
            for (int e = 0; e < NEXP; e++) { if (e == i1) continue; if (lg[e] > lg[i2]) i2 = e; }
            float p2 = expf(lg[i2] - lg[i1]);
            float inv = 1.f / (1.f + p2);
            g_row_tok[warp * 2 + 0] = i1;       // expert ids keyed by (tok,k)
            g_row_tok[warp * 2 + 1] = i2;
            g_row_w[warp * 2 + 0] = inv;        // weights keyed by (tok,k)
            g_row_w[warp * 2 + 1] = p2 * inv;
            atomicAdd(&g_cnt[i1], 1);
            atomicAdd(&g_cnt[i2], 1);
        }
    }
    // ---- tail: last block computes expert offsets ----
    __threadfence();
    __syncthreads();
    if (threadIdx.x == 0) {
        int ticket = atomicAdd(&g_done, 1);
        if (ticket == (int)gridDim.x - 1) {
            int s = 0;
#pragma unroll
            for (int e = 0; e < NEXP; e++) { g_off[e] = s; s += g_cnt[e]; g_fill[e] = 0; }
            g_done = 0;
            __threadfence();
        }
    }
}

__global__ void k_scatter(int T) {
    int i = blockIdx.x * blockDim.x + threadIdx.x;
    if (i >= 2 * T) return;
    int e = g_row_tok[i];
    float w = g_row_w[i];
    int pos = g_off[e] + atomicAdd(&g_fill[e], 1);
    g_tmp_e[pos] = i >> 1;     // token index, gathered order
    g_tmp_w[pos] = w;
}

// ---------------- fused: weight transpose+fp16 (z<24) | zero out (z==24) ----------------
__global__ void k_split_w3(const float* __restrict__ w1, const float* __restrict__ w2,
                           const float* __restrict__ w3, float* __restrict__ outp, long outN4) {
    int lz = blockIdx.z;
    if (lz == 3 * NEXP) {
        // zero the output region with 1024 blocks x 256 threads (FULL 2D block coverage)
        int tid = threadIdx.y * 32 + threadIdx.x;          // R14 bug: ignored threadIdx.y
        long bid = (long)blockIdx.y * 32 + blockIdx.x;
        long i = bid * 256 + tid;
        long stride = 1024L * 256;
        float4 z = make_float4(0.f, 0.f, 0.f, 0.f);
        for (; i < outN4; i += stride) reinterpret_cast<float4*>(outp)[i] = z;
        return;
    }
    __shared__ float t[32][33];
    int layer = lz >> 3, e = lz & 7;
    const float* W = (layer == 0) ? w1 : ((layer == 1) ? w2 : w3);
    int kb = blockIdx.y * 32, nb = blockIdx.x * 32;
    const float* We = W + (size_t)e * H * H;
    int tx = threadIdx.x, ty = threadIdx.y;   // 32 x 8
#pragma unroll
    for (int i = 0; i < 32; i += 8)
        t[ty + i][tx] = We[(size_t)(kb + ty + i) * H + nb + tx];
    __syncthreads();
    size_t obase = ((size_t)layer * NEXP + e) * H * H;
    __half* he = g_wt + obase;
#pragma unroll
    for (int i = 0; i < 32; i += 8)
        he[(size_t)(nb + ty + i) * H + kb + tx] = __float2half(t[tx][ty + i]);
}

// ---------------- HMMA single-pass fp16 gathered expert GEMM ----------------
// R10's compute loop with R7's memory geometry: BK=32, 80B rows, 2-stage cp_wait<0>.
// LAYER 3 accumulates weighted output directly into `out` via atomicAdd
// (exactly 2 fp32 adds per element, commutative -> bit-deterministic).
template <int LAYER>
__global__ __launch_bounds__(256, 2)
void k_gemm_mma(int layer, const float* __restrict__ Bias, float* __restrict__ outp, int T) {
    int e = blockIdx.z;
    int cnt = g_cnt[e];
    int row0 = blockIdx.y * TILE_M;
    if (row0 >= cnt) return;
    int base = g_off[e];
    int col0 = blockIdx.x * TILE_N;
    int tid = threadIdx.x;
    int wid = tid >> 5, lane = tid & 31;
    int wm = wid & 1, wn = wid >> 1;       // warp tile: rows wm*64, cols wn*32
    int r1 = lane >> 2, cq = lane & 3;

    extern __shared__ char smem[];
    uint32_t sb = smem_u32(smem);

    // ---- per-thread load setup (2 threads per row, 32B halves) ----
    int lrow = tid >> 1, lhalf = tid & 1;
    int agrow = row0 + lrow;
    bool aval = (agrow < cnt);
    long aridx = 0;
    if (aval) aridx = (LAYER == 1) ? (long)g_tmp_e[base + agrow] : (long)(base + agrow);
    const __half* pA = (LAYER == 1) ? g_xh : ((LAYER == 2) ? g_a1 : g_a2);
    const char* gA = (const char*)(pA + (size_t)aridx * H) + lhalf * 32;
    uint32_t aSz = aval ? 16u : 0u;   // src-size 0 => zero-fill

    size_t wbase = ((size_t)layer * NEXP + e) * H * H;
    const char* gB = (const char*)(g_wt + wbase + (size_t)(col0 + lrow) * H) + lhalf * 32;

    uint32_t sdstA = sb + OFF_A + lrow * ROWB + lhalf * 32;
    uint32_t sdstB = sb + OFF_B + lrow * ROWB + lhalf * 32;

    // ldmatrix per-thread row offsets (80B stride: conflict-free, R7-verified)
    int lg = lane >> 3, lr = lane & 7;
    uint32_t aRowOff = (uint32_t)((((lg & 1) << 3) + lr) * ROWB + ((lg >> 1) << 4));
    uint32_t bRowOff = (uint32_t)((((lg >> 1) << 3) + lr) * ROWB + ((lg & 1) << 4));
    uint32_t aBase = OFF_A + (uint32_t)(wm * 64) * ROWB + aRowOff;
    uint32_t bBase = OFF_B + (uint32_t)(wn * 32) * ROWB + bRowOff;

    float acc[4][4][4];
#pragma unroll
    for (int i = 0; i < 4; i++)
#pragma unroll
        for (int j = 0; j < 4; j++)
#pragma unroll
            for (int r = 0; r < 4; r++) acc[i][j][r] = 0.f;

    auto loadStage = [&](int kt) {
        uint32_t so = (kt & 1) * STAGE_BYTES;
        long go = (long)kt * 64;           // bytes into row (BK fp16)
        cp16(sdstA + so,      gA + go,      aSz);
        cp16(sdstA + so + 16, gA + go + 16, aSz);
        cp16(sdstB + so,      gB + go,      16u);
        cp16(sdstB + so + 16, gB + go + 16, 16u);
    };

    loadStage(0); cp_commit();

    for (int kt = 0; kt < NK; kt++) {
        cp_wait<0>();
        __syncthreads();
        if (kt + 1 < NK) { loadStage(kt + 1); cp_commit(); }

        uint32_t so = (kt & 1) * STAGE_BYTES;
        uint32_t sA = sb + so + aBase;
        uint32_t sB = sb + so + bBase;

#pragma unroll
        for (int kp = 0; kp < 2; kp++) {
            uint32_t kb = kp * 32;
            uint32_t b[8];
            ldsm4(b + 0, sB + kb);
            ldsm4(b + 4, sB + kb + 16 * ROWB);
#pragma unroll
            for (int i = 0; i < 4; i++) {
                uint32_t a[4];
                ldsm4(a, sA + kb + i * (16 * ROWB));
#pragma unroll
                for (int j = 0; j < 4; j++) mma_f16(acc[i][j], a, b + 2 * j);
            }
        }
        __syncthreads();
    }

    // ---- epilogue ----
    const float* be = Bias + (size_t)e * H + col0 + wn * 32 + cq * 2;
    float2 bj[4];
#pragma unroll
    for (int j = 0; j < 4; j++) bj[j] = *reinterpret_cast<const float2*>(be + j * 8);

#pragma unroll
    for (int i = 0; i < 4; i++) {
        int ra = wm * 64 + i * 16 + r1;
        int rb = ra + 8;
        bool va = (row0 + ra < cnt), vb = (row0 + rb < cnt);
        long oa, ob;
        float wa = 0.f, wb = 0.f;
        if (LAYER == 3) {
            int ta = 0, tb = 0;
            if (va) { ta = g_tmp_e[base + row0 + ra]; wa = g_tmp_w[base + row0 + ra]; }
            if (vb) { tb = g_tmp_e[base + row0 + rb]; wb = g_tmp_w[base + row0 + rb]; }
            oa = (long)ta * H;
            ob = (long)tb * H;
        } else {
            oa = (long)(base + row0 + ra) * H;
            ob = (long)(base + row0 + rb) * H;
        }
#pragma unroll
        for (int j = 0; j < 4; j++) {
            int col = col0 + wn * 32 + j * 8 + cq * 2;
            if (LAYER == 3) {
                if (va) {
                    atomicAdd(outp + oa + col,     wa * (acc[i][j][0] + bj[j].x));
                    atomicAdd(outp + oa + col + 1, wa * (acc[i][j][1] + bj[j].y));
                }
                if (vb) {
                    atomicAdd(outp + ob + col,     wb * (acc[i][j][2] + bj[j].x));
                    atomicAdd(outp + ob + col + 1, wb * (acc[i][j][3] + bj[j].y));
                }
            } else {
                __half* dh = (LAYER == 1) ? g_a1 : g_a2;
                if (va) {
                    float v0 = fmaxf(acc[i][j][0] + bj[j].x, 0.f);
                    float v1 = fmaxf(acc[i][j][1] + bj[j].y, 0.f);
                    *reinterpret_cast<uint32_t*>(dh + oa + col) =
                        pkh(__float2half(v0), __float2half(v1));
                }
                if (vb) {
                    float v0 = fmaxf(acc[i][j][2] + bj[j].x, 0.f);
                    float v1 = fmaxf(acc[i][j][3] + bj[j].y, 0.f);
                    *reinterpret_cast<uint32_t*>(dh + ob + col) =
                        pkh(__float2half(v0), __float2half(v1));
                }
            }
        }
    }
}

// ---------------- counter reset for next replay ----------------
__global__ void k_reset() {
    if (threadIdx.x < NEXP) g_cnt[threadIdx.x] = 0;
}

// ---------------- launch ----------------
// Launch index 3 = k_gemm_mma<1> (ncu -s 5 -c 1 window lands there).
extern "C" void kernel_launch(void* const* d_in, const int* in_sizes, int n_in,
                              void* d_out, int out_size) {
    const float* x  = (const float*)d_in[0];
    const float* gw = (const float*)d_in[1];
    const float* gb = (const float*)d_in[2];
    const float* w1 = (const float*)d_in[3];
    const float* b1 = (const float*)d_in[4];
    const float* w2 = (const float*)d_in[5];
    const float* b2 = (const float*)d_in[6];
    const float* w3 = (const float*)d_in[7];
    const float* b3 = (const float*)d_in[8];
    float* out = (float*)d_out;

    int T = in_sizes[0] / H;
    if (T > MAXT) T = MAXT;
    long outN = (long)T * H;
    bool has_logits = ((long)out_size >= outN + (long)T * NEXP);
    float* logits = has_logits ? out + outN : nullptr;

    cudaFuncSetAttribute(k_gemm_mma<1>, cudaFuncAttributeMaxDynamicSharedMemorySize, SMEM_TOTAL);
    cudaFuncSetAttribute(k_gemm_mma<2>, cudaFuncAttributeMaxDynamicSharedMemorySize, SMEM_TOTAL);
    cudaFuncSetAttribute(k_gemm_mma<3>, cudaFuncAttributeMaxDynamicSharedMemorySize, SMEM_TOTAL);

    k_router<<<(T * 32 + 255) / 256, 256>>>(x, gw, gb, logits, T);     // #0
    k_scatter<<<(2 * T + 255) / 256, 256>>>(T);                        // #1
    dim3 tg(32, 32, 3 * NEXP + 1), tb(32, 8);
    k_split_w3<<<tg, tb>>>(w1, w2, w3, out, outN / 4);                 // #2 (also zeroes out)

    dim3 grid(H / TILE_N, MAXT / TILE_M, NEXP);   // 8 x 64 x 8
    k_gemm_mma<1><<<grid, 256, SMEM_TOTAL>>>(0, b1, nullptr, T);       // #3  <- ncu capture
    k_gemm_mma<2><<<grid, 256, SMEM_TOTAL>>>(1, b2, nullptr, T);       // #4
    k_gemm_mma<3><<<grid, 256, SMEM_TOTAL>>>(2, b3, out, T);           // #5 (direct weighted atomics)

    k_reset<<<1, 32>>>();                                              // #6
}